// round 17
// baseline (speedup 1.0000x reference)
#include <cuda_runtime.h>
#include <math.h>

// ---------------- problem constants (fixed shapes from setup_inputs) -------
#define NB      32          // batch
#define TSAMP   160000      // samples per batch
#define KFFT    1024        // n_fft
#define MWIN    800         // win_length
#define HOP     600
#define NBINS   256
#define NF      267         // 1 + (160000+1024-1024)/600
#define NFQ2    67          // two FFTs (4 frames) per block
#define LMAXW   13
#define LMINW   3
#define FT      (NBINS*NF)  // 68352 (worst-case valid keys per batch)
#define SMEMK   8192        // median smem key cache capacity

#define PHIc(a) ((a) + ((a) >> 4))   // skewed FFT exchange buffer layout
#define TWI(i)  ((i) + ((i) >> 4))   // skewed twiddle index (CF strided reads)

#define FFTBAR(id) asm volatile("bar.sync %0, %1;" :: "r"(id), "r"(64) : "memory")

__device__ __forceinline__ float2 cmul(float2 a, float2 b) {
    return make_float2(a.x * b.x - a.y * b.y, a.x * b.y + a.y * b.x);
}

// ---------------- scratch (__device__ globals, no allocation) --------------
__device__ float        g_Yt[NB*NF*NBINS];      // [B, T, F]: stft-coalesced
__device__ unsigned int g_keys[NB*FT];          // compacted valid keys
__device__ int          g_nvalid[NB];

// ---------------- STFT power: fused-stage-pair radix-4 FFT ------------------
// 64 threads per 1024-pt complex FFT (2 real frames packed), 16 elements per
// thread, ONE exchange buffer per FFT (load-all / named-barrier / write-back
// at each phase). Stages 0+1 fused, exchange, 2+3 fused, exchange, trimmed
// stage 4 + Hermitian unpack. Per-FFT 64-thread named barriers decouple the
// two FFTs sharing a block; 22.8 KB smem + 64-reg cap -> 50% occupancy.
__global__ __launch_bounds__(128, 8) void stft_kernel(const float* __restrict__ y) {
    const int bq  = blockIdx.x % NFQ2;
    const int b   = blockIdx.x / NFQ2;
    const int tid = threadIdx.x;
    const int e   = tid >> 6;                    // FFT slot within block (0/1)
    const int u   = tid & 63;                    // lane within FFT
    const int p   = bq * 2 + e;
    const int fa  = 2 * p;
    const int fb  = 2 * p + 1;                   // may be NF (dropped)
    const int bar = e + 1;                       // named barrier id per FFT

    __shared__ float2 buf[2][1088];              // PHIc(1023)=1086 < 1088
    __shared__ float2 Wt[272];                   // w^j, j<256, TWI-skewed
    __shared__ float  win[MWIN];

    if (bq == 0 && tid == 0) g_nvalid[b] = 0;    // replay-state reset

    {   // twiddle table: exp(-2*pi*i*j/1024), j<256
        float s, c;
        sincospif(-(float)tid / 512.0f, &s, &c);
        Wt[TWI(tid)] = make_float2(c, s);
        sincospif(-(float)(tid + 128) / 512.0f, &s, &c);
        Wt[TWI(tid + 128)] = make_float2(c, s);
    }
    for (int i = tid; i < MWIN; i += 128)        // periodic hann
        win[i] = 0.5f - 0.5f * cospif((float)i / 400.0f);
    __syncthreads();

    float2* Bf = buf[e];
    const float* yb = y + (size_t)b * TSAMP;
    const bool interior = (p >= 1 && p <= 132);
    const float* pa = yb + fa * HOP - 512;
    const float* pb = yb + fb * HOP - 512;

    // ---- phase A: load + fused stages 0+1 -> Bf ----------------------------
    // stage 0 (Ns=1, w=1): group g=u+64a consumes x[g+256c]; per-a loads keep
    // the X working set at 4 float2.
    float2 s0[4][4];
    #pragma unroll
    for (int a = 0; a < 4; a++) {
        float2 xa[4];
        #pragma unroll
        for (int c = 0; c < 4; c++) {
            int j = u + 64 * a + 256 * c;
            float va = 0.0f, vb = 0.0f;
            if (j >= 112 && j < 912) {           // zero-padded centered window
                float w = win[j - 112];
                if (interior) {
                    va = __ldg(pa + j) * w;
                    vb = __ldg(pb + j) * w;
                } else {                         // edge frames: reflect pad
                    int sa = fa * HOP + j - 512; // center=True: pad K/2 = 512
                    if (sa < 0) sa = -sa;
                    else if (sa >= TSAMP) sa = 2 * (TSAMP - 1) - sa;
                    va = __ldg(yb + sa) * w;
                    if (fb < NF) {
                        int sb = fb * HOP + j - 512;
                        if (sb < 0) sb = -sb;
                        else if (sb >= TSAMP) sb = 2 * (TSAMP - 1) - sb;
                        vb = __ldg(yb + sb) * w;
                    }
                }
            }
            xa[c] = make_float2(va, vb);
        }
        float2 t0 = {xa[0].x+xa[2].x, xa[0].y+xa[2].y};
        float2 t1 = {xa[0].x-xa[2].x, xa[0].y-xa[2].y};
        float2 t2 = {xa[1].x+xa[3].x, xa[1].y+xa[3].y};
        float2 t3 = {xa[1].x-xa[3].x, xa[1].y-xa[3].y};
        s0[a][0] = make_float2(t0.x+t2.x, t0.y+t2.y);
        s0[a][1] = make_float2(t1.x+t3.y, t1.y-t3.x);
        s0[a][2] = make_float2(t0.x-t2.x, t0.y-t2.y);
        s0[a][3] = make_float2(t1.x-t3.y, t1.y+t3.x);
    }
    // stage 1 (Ns=4): butterfly k1=4u+r consumes s0[c][r]; writes [16u,16u+16)
    #pragma unroll
    for (int r = 0; r < 4; r++) {
        float2 v0 = s0[0][r], a1 = s0[1][r], a2 = s0[2][r], a3 = s0[3][r];
        if (r > 0) {
            float2 w1 = Wt[TWI(64 * r)];
            float2 w2 = cmul(w1, w1), w3 = cmul(w1, w2);
            a1 = cmul(w1, a1); a2 = cmul(w2, a2); a3 = cmul(w3, a3);
        }
        float2 t0 = {v0.x+a2.x, v0.y+a2.y}, t1 = {v0.x-a2.x, v0.y-a2.y};
        float2 t2 = {a1.x+a3.x, a1.y+a3.y}, t3 = {a1.x-a3.x, a1.y-a3.y};
        const int base = 16 * u + r;
        Bf[PHIc(base)]      = make_float2(t0.x+t2.x, t0.y+t2.y);
        Bf[PHIc(base + 4)]  = make_float2(t1.x+t3.y, t1.y-t3.x);
        Bf[PHIc(base + 8)]  = make_float2(t0.x-t2.x, t0.y-t2.y);
        Bf[PHIc(base + 12)] = make_float2(t1.x-t3.y, t1.y+t3.x);
    }
    FFTBAR(bar);

    // ---- phase B: fused stages 2+3 (load all, barrier, write back) ---------
    const int m2 = u & 15, q2 = u >> 4;
    float2 V[4][4];
    #pragma unroll
    for (int c1 = 0; c1 < 4; c1++)
    #pragma unroll
    for (int d = 0; d < 4; d++)
        V[c1][d] = Bf[PHIc(u + 64 * c1 + 256 * d)];
    FFTBAR(bar);                                 // all reads done before writes

    float2 s2[4][4];
    {
        float2 w1 = Wt[TWI(16 * m2)];
        float2 w2 = cmul(w1, w1), w3 = cmul(w1, w2);
        #pragma unroll
        for (int c1 = 0; c1 < 4; c1++) {
            float2 v0 = V[c1][0];
            float2 a1 = cmul(w1, V[c1][1]);
            float2 a2 = cmul(w2, V[c1][2]);
            float2 a3 = cmul(w3, V[c1][3]);
            float2 t0 = {v0.x+a2.x, v0.y+a2.y}, t1 = {v0.x-a2.x, v0.y-a2.y};
            float2 t2 = {a1.x+a3.x, a1.y+a3.y}, t3 = {a1.x-a3.x, a1.y-a3.y};
            s2[c1][0] = make_float2(t0.x+t2.x, t0.y+t2.y);
            s2[c1][1] = make_float2(t1.x+t3.y, t1.y-t3.x);
            s2[c1][2] = make_float2(t0.x-t2.x, t0.y-t2.y);
            s2[c1][3] = make_float2(t1.x-t3.y, t1.y+t3.x);
        }
    }
    #pragma unroll
    for (int c = 0; c < 4; c++) {                // stage 3: m3 = m2+16c
        float2 w1 = Wt[TWI(4 * m2 + 64 * c)];
        float2 w2 = cmul(w1, w1), w3 = cmul(w1, w2);
        float2 v0 = s2[0][c];
        float2 a1 = cmul(w1, s2[1][c]);
        float2 a2 = cmul(w2, s2[2][c]);
        float2 a3 = cmul(w3, s2[3][c]);
        float2 t0 = {v0.x+a2.x, v0.y+a2.y}, t1 = {v0.x-a2.x, v0.y-a2.y};
        float2 t2 = {a1.x+a3.x, a1.y+a3.y}, t3 = {a1.x-a3.x, a1.y-a3.y};
        const int base = 256 * q2 + m2 + 16 * c;
        Bf[PHIc(base)]       = make_float2(t0.x+t2.x, t0.y+t2.y);
        Bf[PHIc(base + 64)]  = make_float2(t1.x+t3.y, t1.y-t3.x);
        Bf[PHIc(base + 128)] = make_float2(t0.x-t2.x, t0.y-t2.y);
        Bf[PHIc(base + 192)] = make_float2(t1.x-t3.y, t1.y+t3.x);
    }
    FFTBAR(bar);

    // ---- phase C: stage 4 (Ns=256, trimmed): Z[k4], Z[k4+768] only ---------
    float2 Vz[4][4];
    #pragma unroll
    for (int d = 0; d < 4; d++)
    #pragma unroll
    for (int c = 0; c < 4; c++)
        Vz[d][c] = Bf[PHIc(u + 64 * d + 256 * c)];
    FFTBAR(bar);                                 // reads done before unskewed writes

    #pragma unroll
    for (int d = 0; d < 4; d++) {
        const int k4 = u + 64 * d;
        float2 w1 = Wt[TWI(k4)];
        float2 w2 = cmul(w1, w1), w3 = cmul(w1, w2);
        float2 v0 = Vz[d][0];
        float2 a1 = cmul(w1, Vz[d][1]);
        float2 a2 = cmul(w2, Vz[d][2]);
        float2 a3 = cmul(w3, Vz[d][3]);
        float2 t0 = {v0.x+a2.x, v0.y+a2.y}, t1 = {v0.x-a2.x, v0.y-a2.y};
        float2 t2 = {a1.x+a3.x, a1.y+a3.y}, t3 = {a1.x-a3.x, a1.y-a3.y};
        Bf[k4]       = make_float2(t0.x+t2.x, t0.y+t2.y);   // Z[k4]
        Bf[256 + k4] = make_float2(t1.x-t3.y, t1.y+t3.x);   // Z[k4+768]
    }
    FFTBAR(bar);

    // ---- Hermitian unpack; power, layout [B, T, F] -------------------------
    float* Ya = g_Yt + ((size_t)b * NF + fa) * NBINS;
    float* Yb = g_Yt + ((size_t)b * NF + fb) * NBINS;
    #pragma unroll
    for (int i = 0; i < 4; i++) {
        const int k = u + 64 * i;
        float2 zk = Bf[k];
        float2 zc = (k == 0) ? zk : Bf[512 - k];  // Z[1024-k] = Zhi[256-k]
        float xar = 0.5f * (zk.x + zc.x), xai = 0.5f * (zk.y - zc.y);
        float ddr = zk.x - zc.x,          ddi = zk.y + zc.y;
        float xbr = 0.5f * ddi,           xbi = -0.5f * ddr;
        Ya[k] = xar * xar + xai * xai;
        if (fb < NF) Yb[k] = xbr * xbr + xbi * xbi;
    }
}

// ---------------- RT60 per (batch, subband): compact valid keys -------------
__global__ __launch_bounds__(128) void rt60_kernel() {
    const int f = blockIdx.x % NBINS;
    const int b = blockIdx.x / NBINS;
    __shared__ float        sy[NF];
    __shared__ unsigned int W[12];               // decrease-flag bitmask (267 bits)
    __shared__ unsigned int skey[NF];
    __shared__ int          sbest;
    __shared__ int          scnt;
    __shared__ int          sbase;
    const int tid  = threadIdx.x;
    const int lane = tid & 31;
    if (tid < 12) W[tid] = 0u;
    if (tid == 0) { sbest = 0; scnt = 0; }

    const float* col = g_Yt + (size_t)b * NF * NBINS + f;
    for (int t = tid; t < NF; t += 128) sy[t] = __ldg(col + (size_t)t * NBINS);
    __syncthreads();

    // pack strict-decrease flags into bitmask words via ballot
    #pragma unroll
    for (int base = 0; base < 288; base += 128) {
        int t = base + tid;
        bool flag = (t + 1 < NF) && (sy[t + 1] < sy[t]);
        unsigned int m = __ballot_sync(0xFFFFFFFFu, flag);
        if (lane == 0 && (t >> 5) < 9) W[t >> 5] = m;
    }
    __syncthreads();

    // best window length: run length from t = ffs of first zero bit
    int localbest = 0;
    for (int t = tid; t < NF; t += 128) {
        int w = t >> 5, r = t & 31;
        unsigned int bits = (W[w] >> r) | (r ? (W[w + 1] << (32 - r)) : 0u);
        unsigned int nb = ~bits;
        int c = nb ? (__ffs(nb) - 1) : 32;
        if (c > LMAXW - 1) c = LMAXW - 1;
        int cand = c + 1;
        int rem  = NF - t;
        if (cand > rem) cand = rem;
        if (cand > localbest) localbest = cand;
    }
    atomicMax(&sbest, localbest);
    __syncthreads();

    const int lenL = sbest;
    if (lenL < LMINW) return;                    // no decreasing window at all

    const float xm  = 0.5f * (float)(lenL - 1);
    const float den = (float)lenL * (float)(lenL * lenL - 1) / 12.0f;

    for (int t = tid; t < NF; t += 128) {
        int w = t >> 5, r = t & 31;
        unsigned int bits = (W[w] >> r) | (r ? (W[w + 1] << (32 - r)) : 0u);
        unsigned int nb = ~bits;
        int c = nb ? (__ffs(nb) - 1) : 32;
        if (t + lenL <= NF && c >= lenL - 1) {
            // EDC: reverse cumsum in same order as reference, then dB
            float acc = 0.0f;
            float db[LMAXW];
            for (int j = lenL - 1; j >= 0; j--) {
                acc += sy[t + j];
                db[j] = 10.0f * log10f(fmaxf(acc, 1e-10f));
            }
            float d0 = db[0];
            if (db[lenL - 1] - d0 < -10.0f) {    // selected
                float num = 0.0f;
                for (int j = 1; j < lenL; j++)
                    num += ((float)j - xm) * (db[j] - d0);
                float slope = num / den;         // slope <= 0 here
                float rt60  = (-60.0f / slope) * 0.0375f;  // HOP/FS
                unsigned int uu = __float_as_uint(rt60);
                unsigned int key = (uu & 0x80000000u) ? ~uu : (uu | 0x80000000u);
                int pos = atomicAdd(&scnt, 1);   // smem atomic (cheap)
                skey[pos] = key;
            }
        }
    }
    __syncthreads();

    const int cnt = scnt;
    if (cnt == 0) return;
    if (tid == 0) sbase = atomicAdd(&g_nvalid[b], cnt);  // ONE global atomic
    __syncthreads();
    unsigned int* dst = g_keys + (size_t)b * FT + sbase;
    for (int i = tid; i < cnt; i += 128) dst[i] = skey[i];
}

// ---------------- median: one block per batch, 4-pass radix select ----------
__global__ __launch_bounds__(512) void median_kernel(const float* __restrict__ coeffs,
                                                     float* __restrict__ out) {
    const int b   = blockIdx.x;
    const int tid = threadIdx.x;
    __shared__ unsigned int skeys[SMEMK];
    __shared__ int          hist[256];
    __shared__ unsigned int s_pfx;
    __shared__ int          s_k;

    const int n = g_nvalid[b];
    if (n == 0) {
        if (tid == 0) out[b] = 0.5f;             // DEFAULT_RT60 (>= 0.01)
        return;
    }
    const unsigned int* gk = g_keys + (size_t)b * FT;
    const bool fits = (n <= SMEMK);
    if (fits)
        for (int i = tid; i < n; i += 512) skeys[i] = gk[i];
    if (tid == 0) { s_pfx = 0u; s_k = (n - 1) >> 1; }
    __syncthreads();

    #pragma unroll
    for (int pass = 0; pass < 4; pass++) {
        for (int i = tid; i < 256; i += 512) hist[i] = 0;
        __syncthreads();
        const int shift = 24 - 8 * pass;
        const unsigned int pfx   = s_pfx;
        const unsigned int hmask = (pass == 0) ? 0u : (0xFFFFFFFFu << (shift + 8));
        if (fits) {
            for (int i = tid; i < n; i += 512) {
                unsigned int key = skeys[i];
                if ((key & hmask) == pfx) atomicAdd(&hist[(key >> shift) & 255], 1);
            }
        } else {
            for (int i = tid; i < n; i += 512) {
                unsigned int key = gk[i];
                if ((key & hmask) == pfx) atomicAdd(&hist[(key >> shift) & 255], 1);
            }
        }
        __syncthreads();

        if (tid < 32) {                          // warp-scan bin select
            const int lane = tid;
            const int base = lane * 8;
            int c[8]; int s = 0;
            #pragma unroll
            for (int q = 0; q < 8; q++) { c[q] = hist[base + q]; s += c[q]; }
            int excl = s;
            #pragma unroll
            for (int off = 1; off < 32; off <<= 1) {
                int nn = __shfl_up_sync(0xFFFFFFFFu, excl, off);
                if (lane >= off) excl += nn;
            }
            excl -= s;                           // exclusive prefix across lanes
            const int k0 = s_k;
            int bin = 256, cumAt = 0, cum = excl;
            #pragma unroll
            for (int q = 0; q < 8; q++) {
                if (bin == 256 && cum + c[q] > k0) { bin = base + q; cumAt = cum; }
                cum += c[q];
            }
            unsigned int ball = __ballot_sync(0xFFFFFFFFu, bin < 256);
            int src = __ffs(ball) - 1;           // guaranteed: total >= k0+1
            if (lane == src) {
                s_k   = k0 - cumAt;
                s_pfx = pfx | ((unsigned int)bin << shift);
            }
        }
        __syncthreads();
    }

    if (tid == 0) {
        unsigned int key = s_pfx;
        unsigned int u = (key & 0x80000000u) ? (key ^ 0x80000000u) : ~key;
        float med = __uint_as_float(u);
        out[b] = fmaxf(coeffs[0] + coeffs[1] * med, 0.01f);
    }
}

// ---------------- launcher ---------------------------------------------------
extern "C" void kernel_launch(void* const* d_in, const int* in_sizes, int n_in,
                              void* d_out, int out_size) {
    const float* y      = (const float*)d_in[0];
    const float* coeffs = (const float*)d_in[1];
    float*       out    = (float*)d_out;

    stft_kernel<<<NB * NFQ2, 128>>>(y);
    rt60_kernel<<<NB * NBINS, 128>>>();
    median_kernel<<<NB, 512>>>(coeffs, out);
}